// round 6
// baseline (speedup 1.0000x reference)
#include <cuda_runtime.h>
#include <cstdint>
#include <math.h>

// Problem shape
#define S_LEN   512
#define D_HEAD  64
#define BHC     128
#define NV      3

// ---------------------------------------------------------------------------
// Threefry-2x32, key (0,42), partitionable fold out0^out1 (bit-exact, R2/R4/R5)
// ---------------------------------------------------------------------------
#define TF_R(r) do { x0 += x1; x1 = __funnelshift_l(x1, x1, (r)); x1 ^= x0; } while (0)

__device__ __forceinline__ uint32_t threefry_word(uint32_t c1) {
    const uint32_t ks1 = 42u;
    const uint32_t ks2 = 0x1BD11BDAu ^ 42u;
    uint32_t x0 = 0u;
    uint32_t x1 = c1 + ks1;
    TF_R(13); TF_R(15); TF_R(26); TF_R(6);
    x0 += ks1; x1 += ks2 + 1u;
    TF_R(17); TF_R(29); TF_R(16); TF_R(24);
    x0 += ks2; x1 += 0u + 2u;
    TF_R(13); TF_R(15); TF_R(26); TF_R(6);
    x0 += 0u; x1 += ks1 + 3u;
    TF_R(17); TF_R(29); TF_R(16); TF_R(24);
    x0 += ks1; x1 += ks2 + 4u;
    TF_R(13); TF_R(15); TF_R(26); TF_R(6);
    x0 += ks2; x1 += 0u + 5u;
    return x0 ^ x1;
}
// keep <=> uniform(bits) < 0.65f <=> bits < 0xA6666600 (exact integer form)
#define KEEP(bits) ((bits) < 0xA6666600u)

// ---------------------------------------------------------------------------
// mma.sync helpers (sm_80-level PTX, legal on compute_103)
// ---------------------------------------------------------------------------
__device__ __forceinline__ uint32_t smem_u32(const void* p) {
    uint32_t a;
    asm("{ .reg .u64 t; cvta.to.shared.u64 t, %1; cvt.u32.u64 %0, t; }" : "=r"(a) : "l"(p));
    return a;
}
__device__ __forceinline__ float rna_tf32(float x) {
    uint32_t u;
    asm("cvt.rna.tf32.f32 %0, %1;" : "=r"(u) : "f"(x));
    return __uint_as_float(u);
}

#define LDSM4(r0, r1, r2, r3, addr)                                          \
    asm volatile("ldmatrix.sync.aligned.m8n8.x4.shared.b16 {%0,%1,%2,%3}, [%4];" \
        : "=r"(r0), "=r"(r1), "=r"(r2), "=r"(r3) : "r"(addr))

#define MMA8(c, a, b0, b1)                                                   \
    asm volatile("mma.sync.aligned.m16n8k8.row.col.f32.tf32.tf32.f32 "       \
        "{%0,%1,%2,%3}, {%4,%5,%6,%7}, {%8,%9}, {%0,%1,%2,%3};"              \
        : "+f"((c)[0]), "+f"((c)[1]), "+f"((c)[2]), "+f"((c)[3])             \
        : "r"((a)[0]), "r"((a)[1]), "r"((a)[2]), "r"((a)[3]),                \
          "r"(b0), "r"(b1))

// SMEM layout (float offsets), row stride 68 floats
#define LD   68
#define QHI  0
#define QLO  8704
#define KHI  17408
#define KLO  21760
#define VT   26112
#define PS   39168
#define RS   47872
#define SM_FLOATS 48000   // 192000 bytes

__global__ void __launch_bounds__(512, 1)
attn_mma(const float* __restrict__ t0, const float* __restrict__ t1,
         const float* __restrict__ t2, const float* __restrict__ t3,
         float* __restrict__ out) {
    extern __shared__ float smf[];
    const uint32_t sb = smem_u32(smf);
    const int tid = threadIdx.x, wid = tid >> 5, lane = tid & 31;
    const int g = lane >> 2, i4 = lane & 3;
    const int bh = blockIdx.x >> 2, q0 = (blockIdx.x & 3) << 7;
    const float scale = *t3;

    // MMA1 warp tile: 16q x 32k ; MMA2 warp tile: 32q x 48d
    const int qb1 = (wid >> 1) << 4, kb1 = (wid & 1) << 5;
    const int qb2 = (wid >> 2) << 5, db2 = (wid & 3) * 48;

    const int ar = lane & 15, ac = (lane >> 4) << 2;   // ldmatrix A pattern
    const int br = lane & 7,  bc = (lane >> 3) << 2;   // ldmatrix B pattern

    const uint32_t rowbase = (uint32_t)(bh * S_LEN + q0);

    // 8 mask bits for rows (qb1 + 8*dr + g), cols kt*64 + kb1 + {8nt+2i4, +1}
    auto mask_half = [&](int kt, int dr) -> uint32_t {
        uint32_t c0 = (rowbase + (uint32_t)(qb1 + 8 * dr + g)) * 512u
                    + (uint32_t)(kt * 64 + kb1 + 2 * i4);
        uint32_t m = 0u;
#pragma unroll
        for (int nt = 0; nt < 4; nt++) {
            m |= (KEEP(threefry_word(c0 + 8u * nt))      ? 1u : 0u) << (2 * nt);
            m |= (KEEP(threefry_word(c0 + 8u * nt + 1u)) ? 1u : 0u) << (2 * nt + 1);
        }
        return m;
    };

    if (tid < 128) smf[RS + tid] = 0.0f;

    // mask(0): ALU chains fill the LDG stall slots of the Q/K/V prologue loads
    uint32_t mcur = mask_half(0, 0) | (mask_half(0, 1) << 8);

    // ---- Q [128,64] -> hi/lo ----
    const float* Qg = t0 + ((size_t)bh * S_LEN + q0) * D_HEAD;
#pragma unroll
    for (int i = 0; i < 4; i++) {
        int idx = tid + (i << 9);
        int r = idx >> 4, d4 = (idx & 15) << 2;
        float4 x = *(const float4*)(Qg + r * D_HEAD + d4);
        float4 h, l;
        h.x = rna_tf32(x.x); l.x = rna_tf32(x.x - h.x);
        h.y = rna_tf32(x.y); l.y = rna_tf32(x.y - h.y);
        h.z = rna_tf32(x.z); l.z = rna_tf32(x.z - h.z);
        h.w = rna_tf32(x.w); l.w = rna_tf32(x.w - h.w);
        *(float4*)(smf + QHI + r * LD + d4) = h;
        *(float4*)(smf + QLO + r * LD + d4) = l;
    }

    const float* Kg = t1 + (size_t)bh * S_LEN * D_HEAD;
    const float* Vg = t2 + (size_t)bh * NV * S_LEN * D_HEAD;

    auto storeK = [&](float4 x, int idx) {
        int r = idx >> 4, d4 = (idx & 15) << 2;
        float4 h, l;
        h.x = rna_tf32(x.x); l.x = rna_tf32(x.x - h.x);
        h.y = rna_tf32(x.y); l.y = rna_tf32(x.y - h.y);
        h.z = rna_tf32(x.z); l.z = rna_tf32(x.z - h.z);
        h.w = rna_tf32(x.w); l.w = rna_tf32(x.w - h.w);
        *(float4*)(smf + KHI + r * LD + d4) = h;
        *(float4*)(smf + KLO + r * LD + d4) = l;
    };
    auto ldK = [&](int kt, int idx) {
        int r = idx >> 4, d4 = (idx & 15) << 2;
        return *(const float4*)(Kg + (size_t)(kt * 64 + r) * D_HEAD + d4);
    };
    // V tile: VT[d][k], thread handles chunk (d, 4 consecutive k)
    auto loadV = [&](int kt) {
#pragma unroll
        for (int i = 0; i < 6; i++) {
            int c = tid + (i << 9);          // 3072 chunks: 192 d x 16 kgroups
            int kg = c / 192, d = c - kg * 192;
            int v = d >> 6, dl = d & 63;
            const float* p = Vg + (((size_t)v * S_LEN) + kt * 64 + kg * 4) * D_HEAD + dl;
            float4 w;
            w.x = rna_tf32(p[0]);
            w.y = rna_tf32(p[64]);
            w.z = rna_tf32(p[128]);
            w.w = rna_tf32(p[192]);
            *(float4*)(smf + VT + d * LD + kg * 4) = w;
        }
    };

    {   // K(0), V(0)
#pragma unroll
        for (int i = 0; i < 2; i++) storeK(ldK(0, tid + (i << 9)), tid + (i << 9));
        loadV(0);
    }
    __syncthreads();

    float o[2][6][4];
#pragma unroll
    for (int a = 0; a < 2; a++)
#pragma unroll
        for (int b = 0; b < 6; b++)
#pragma unroll
            for (int c = 0; c < 4; c++) o[a][b][c] = 0.0f;
    float rs2[2] = {0.0f, 0.0f};

    for (int kt = 0; kt < 8; kt++) {
        // --- half A of mask(kt+1): independent ALU, interleaves with MMA1 ---
        uint32_t mnA = (kt < 7) ? mask_half(kt + 1, 0) : 0u;

        // ============ MMA1: S[128,64] = Q K^T (3x tf32 split) =============
        float s[4][4];
#pragma unroll
        for (int b = 0; b < 4; b++)
#pragma unroll
            for (int c = 0; c < 4; c++) s[b][c] = 0.0f;

#pragma unroll
        for (int kp = 0; kp < 4; kp++) {
            uint32_t bhi[4][4], blo[4][4];
#pragma unroll
            for (int nt = 0; nt < 4; nt++) {
                uint32_t rowoff = (uint32_t)((kb1 + 8 * nt + br) * LD + kp * 16 + bc);
                LDSM4(bhi[nt][0], bhi[nt][1], bhi[nt][2], bhi[nt][3], sb + ((KHI + rowoff) << 2));
                LDSM4(blo[nt][0], blo[nt][1], blo[nt][2], blo[nt][3], sb + ((KLO + rowoff) << 2));
            }
#pragma unroll
            for (int sub = 0; sub < 2; sub++) {
                int ks = kp * 2 + sub;
                uint32_t ah[4], al[4];
                uint32_t rowoff = (uint32_t)((qb1 + ar) * LD + ks * 8 + ac);
                LDSM4(ah[0], ah[1], ah[2], ah[3], sb + ((QHI + rowoff) << 2));
                LDSM4(al[0], al[1], al[2], al[3], sb + ((QLO + rowoff) << 2));
#pragma unroll
                for (int nt = 0; nt < 4; nt++) {
                    MMA8(s[nt], ah, bhi[nt][2 * sub], bhi[nt][2 * sub + 1]);
                    MMA8(s[nt], al, bhi[nt][2 * sub], bhi[nt][2 * sub + 1]);
                    MMA8(s[nt], ah, blo[nt][2 * sub], blo[nt][2 * sub + 1]);
                }
            }
        }

        // ============ softmax + dropout (mask from mcur) -> P ==============
#pragma unroll
        for (int dr = 0; dr < 2; dr++) {
            int row = qb1 + 8 * dr + g;
            float psum = 0.0f;
#pragma unroll
            for (int nt = 0; nt < 4; nt++) {
                float e0 = __expf(s[nt][dr * 2 + 0] * scale);
                float e1 = __expf(s[nt][dr * 2 + 1] * scale);
                psum += e0 + e1;
                uint32_t b2 = mcur >> (dr * 8 + nt * 2);
                float2 pr;
                pr.x = (b2 & 1u) ? rna_tf32(e0) : 0.0f;
                pr.y = (b2 & 2u) ? rna_tf32(e1) : 0.0f;
                *(float2*)(smf + PS + row * LD + kb1 + 8 * nt + 2 * i4) = pr;
            }
            rs2[dr] += psum;
        }
        __syncthreads();   // barrier 1: P visible; K smem free (MMA1 done)

        // --- half B of mask(kt+1): interleaves with K prefetch + MMA2 ---
        uint32_t mnB = (kt < 7) ? mask_half(kt + 1, 1) : 0u;

        // prefetch K(kt+1) into registers (hidden under MMA2)
        float4 kreg0, kreg1;
        if (kt < 7) {
            kreg0 = ldK(kt + 1, tid);
            kreg1 = ldK(kt + 1, tid + 512);
        }

        // ============ MMA2: O[128,192] += P V ============================
#pragma unroll
        for (int kp = 0; kp < 4; kp++) {
            uint32_t bv[6][4];
#pragma unroll
            for (int nt = 0; nt < 6; nt++) {
                uint32_t rowoff = (uint32_t)((db2 + 8 * nt + br) * LD + kp * 16 + bc);
                LDSM4(bv[nt][0], bv[nt][1], bv[nt][2], bv[nt][3], sb + ((VT + rowoff) << 2));
            }
#pragma unroll
            for (int sub = 0; sub < 2; sub++) {
                int ks = kp * 2 + sub;
                uint32_t ap[2][4];
#pragma unroll
                for (int mt = 0; mt < 2; mt++) {
                    uint32_t rowoff = (uint32_t)((qb2 + 16 * mt + ar) * LD + ks * 8 + ac);
                    LDSM4(ap[mt][0], ap[mt][1], ap[mt][2], ap[mt][3], sb + ((PS + rowoff) << 2));
                }
#pragma unroll
                for (int mt = 0; mt < 2; mt++)
#pragma unroll
                    for (int nt = 0; nt < 6; nt++)
                        MMA8(o[mt][nt], ap[mt], bv[nt][2 * sub], bv[nt][2 * sub + 1]);
            }
        }

        if (kt < 7) {
            storeK(kreg0, tid);
            storeK(kreg1, tid + 512);
        }
        __syncthreads();   // barrier 2: MMA2 smem reads done; K(kt+1) visible

        if (kt < 7) loadV(kt + 1);   // overlaps next MMA1; ordered by barrier 1

        mcur = mnA | (mnB << 8);
    }

    // ---- row-sum reduction (denominator includes dropped elems) ----
#pragma unroll
    for (int dr = 0; dr < 2; dr++) {
        float v = rs2[dr];
        v += __shfl_xor_sync(0xffffffffu, v, 1);
        v += __shfl_xor_sync(0xffffffffu, v, 2);
        if (i4 == 0) atomicAdd(&smf[RS + qb1 + 8 * dr + g], v);
    }
    __syncthreads();
    if (tid < 128) smf[RS + tid] = 1.0f / (smf[RS + tid] * 0.65f);
    __syncthreads();

    // ---- epilogue: normalize + store ----
#pragma unroll
    for (int mt = 0; mt < 2; mt++)
#pragma unroll
        for (int dr = 0; dr < 2; dr++) {
            int row = qb2 + 16 * mt + 8 * dr + g;
            float inv = smf[RS + row];
#pragma unroll
            for (int nt = 0; nt < 6; nt++) {
                int col = db2 + 8 * nt + 2 * i4;
                int v = col >> 6, d = col & 63;
                float2 w;
                w.x = o[mt][nt][dr * 2 + 0] * inv;
                w.y = o[mt][nt][dr * 2 + 1] * inv;
                *(float2*)(out + (((size_t)bh * NV + v) * S_LEN + q0 + row) * D_HEAD + d) = w;
            }
        }
}

// ---------------------------------------------------------------------------
extern "C" void kernel_launch(void* const* d_in, const int* in_sizes, int n_in,
                              void* d_out, int out_size) {
    const float* t0 = (const float*)d_in[0];
    const float* t1 = (const float*)d_in[1];
    const float* t2 = (const float*)d_in[2];
    const float* t3 = (const float*)d_in[3];
    float* out = (float*)d_out;

    static bool attr_set = false;
    if (!attr_set) {
        cudaFuncSetAttribute(attn_mma, cudaFuncAttributeMaxDynamicSharedMemorySize,
                             SM_FLOATS * (int)sizeof(float));
        attr_set = true;
    }

    attn_mma<<<BHC * 4, 512, SM_FLOATS * sizeof(float)>>>(t0, t1, t2, t3, out);
}

// round 7
// speedup vs baseline: 1.5719x; 1.5719x over previous
#include <cuda_runtime.h>
#include <cstdint>
#include <math.h>

// Problem shape
#define S_LEN   512
#define D_HEAD  64
#define BHC     128
#define NV      3

// ---------------------------------------------------------------------------
// Threefry-2x32, key (0,42), partitionable fold out0^out1 (bit-exact R2/R4/R5)
// ---------------------------------------------------------------------------
#define TF_R(r) do { x0 += x1; x1 = __funnelshift_l(x1, x1, (r)); x1 ^= x0; } while (0)

__device__ __forceinline__ uint32_t threefry_word(uint32_t c1) {
    const uint32_t ks1 = 42u;
    const uint32_t ks2 = 0x1BD11BDAu ^ 42u;
    uint32_t x0 = 0u;
    uint32_t x1 = c1 + ks1;
    TF_R(13); TF_R(15); TF_R(26); TF_R(6);
    x0 += ks1; x1 += ks2 + 1u;
    TF_R(17); TF_R(29); TF_R(16); TF_R(24);
    x0 += ks2; x1 += 0u + 2u;
    TF_R(13); TF_R(15); TF_R(26); TF_R(6);
    x0 += 0u; x1 += ks1 + 3u;
    TF_R(17); TF_R(29); TF_R(16); TF_R(24);
    x0 += ks1; x1 += ks2 + 4u;
    TF_R(13); TF_R(15); TF_R(26); TF_R(6);
    x0 += ks2; x1 += 0u + 5u;
    return x0 ^ x1;
}
// keep <=> uniform(bits) < 0.65f <=> bits < 0xA6666600 (exact integer form)
#define KEEP(bits) ((bits) < 0xA6666600u)

// ---------------------------------------------------------------------------
// mma.sync helpers (sm_80-level PTX, legal on compute_103)
// ---------------------------------------------------------------------------
__device__ __forceinline__ uint32_t smem_u32(const void* p) {
    uint32_t a;
    asm("{ .reg .u64 t; cvta.to.shared.u64 t, %1; cvt.u32.u64 %0, t; }" : "=r"(a) : "l"(p));
    return a;
}
__device__ __forceinline__ float rna_tf32(float x) {
    uint32_t u;
    asm("cvt.rna.tf32.f32 %0, %1;" : "=r"(u) : "f"(x));
    return __uint_as_float(u);
}

#define LDSM4(r0, r1, r2, r3, addr)                                          \
    asm volatile("ldmatrix.sync.aligned.m8n8.x4.shared.b16 {%0,%1,%2,%3}, [%4];" \
        : "=r"(r0), "=r"(r1), "=r"(r2), "=r"(r3) : "r"(addr))

#define MMA8(c, a, b0, b1)                                                   \
    asm volatile("mma.sync.aligned.m16n8k8.row.col.f32.tf32.tf32.f32 "       \
        "{%0,%1,%2,%3}, {%4,%5,%6,%7}, {%8,%9}, {%0,%1,%2,%3};"              \
        : "+f"((c)[0]), "+f"((c)[1]), "+f"((c)[2]), "+f"((c)[3])             \
        : "r"((a)[0]), "r"((a)[1]), "r"((a)[2]), "r"((a)[3]),                \
          "r"(b0), "r"(b1))

// SMEM layout (float offsets), row stride 68 floats. Total 104704 bytes.
#define LD   68
#define QHI  0
#define QLO  4352
#define KHI  8704
#define KLO  13056
#define VT   17408
#define PS   21760
#define RS   26112
#define SM_FLOATS 26176

__global__ void __launch_bounds__(256, 2)
attn_mma(const float* __restrict__ t0, const float* __restrict__ t1,
         const float* __restrict__ t2, const float* __restrict__ t3,
         float* __restrict__ out) {
    extern __shared__ float smf[];
    const uint32_t sb = smem_u32(smf);
    const int tid = threadIdx.x, wid = tid >> 5, lane = tid & 31;
    const int g = lane >> 2, i4 = lane & 3;
    const int bh = blockIdx.x >> 3, q0 = (blockIdx.x & 7) << 6;
    const float scale = *t3;

    // warp tile (both GEMMs): 16 q-rows x 32 cols
    const int qb1 = (wid >> 1) << 4, kb1 = (wid & 1) << 5;

    const int ar = lane & 15, ac = (lane >> 4) << 2;   // ldmatrix A pattern
    const int br = lane & 7,  bc = (lane >> 3) << 2;   // ldmatrix B pattern

    const uint32_t rowbase = (uint32_t)(bh * S_LEN + q0);

    if (tid < 64) smf[RS + tid] = 0.0f;

    // ---- Q [64,64] -> hi/lo ----
    const float* Qg = t0 + ((size_t)bh * S_LEN + q0) * D_HEAD;
#pragma unroll
    for (int i = 0; i < 4; i++) {
        int idx = tid + (i << 8);
        int r = idx >> 4, d4 = (idx & 15) << 2;
        float4 x = *(const float4*)(Qg + r * D_HEAD + d4);
        float4 h, l;
        h.x = rna_tf32(x.x); l.x = rna_tf32(x.x - h.x);
        h.y = rna_tf32(x.y); l.y = rna_tf32(x.y - h.y);
        h.z = rna_tf32(x.z); l.z = rna_tf32(x.z - h.z);
        h.w = rna_tf32(x.w); l.w = rna_tf32(x.w - h.w);
        *(float4*)(smf + QHI + r * LD + d4) = h;
        *(float4*)(smf + QLO + r * LD + d4) = l;
    }

    const float* Kg = t1 + (size_t)bh * S_LEN * D_HEAD;
    const float* Vg = t2 + (size_t)bh * NV * S_LEN * D_HEAD;

    auto ldK = [&](int kt, int i, float4* kr) {
        int idx = tid + (i << 8);
        int r = idx >> 4, d4 = (idx & 15) << 2;
        kr[i] = *(const float4*)(Kg + (size_t)(kt * 64 + r) * D_HEAD + d4);
    };
    auto stK = [&](int i, const float4* kr) {
        int idx = tid + (i << 8);
        int r = idx >> 4, d4 = (idx & 15) << 2;
        float4 x = kr[i], h, l;
        h.x = rna_tf32(x.x); l.x = rna_tf32(x.x - h.x);
        h.y = rna_tf32(x.y); l.y = rna_tf32(x.y - h.y);
        h.z = rna_tf32(x.z); l.z = rna_tf32(x.z - h.z);
        h.w = rna_tf32(x.w); l.w = rna_tf32(x.w - h.w);
        *(float4*)(smf + KHI + r * LD + d4) = h;
        *(float4*)(smf + KLO + r * LD + d4) = l;
    };
    // V chunk (kt, v): VT[d][k] transposed, 64x64. 4 float4 per thread.
    auto ldV = [&](int kt, int v, float4* vr) {
#pragma unroll
        for (int i = 0; i < 4; i++) {
            int c = tid + (i << 8);
            int d = c & 63, kg = c >> 6;
            const float* p = Vg + (((size_t)v * S_LEN) + kt * 64 + kg * 4) * D_HEAD + d;
            float4 w;
            w.x = rna_tf32(p[0]);
            w.y = rna_tf32(p[64]);
            w.z = rna_tf32(p[128]);
            w.w = rna_tf32(p[192]);
            vr[i] = w;
        }
    };
    auto stV = [&](const float4* vr) {
#pragma unroll
        for (int i = 0; i < 4; i++) {
            int c = tid + (i << 8);
            int d = c & 63, kg = c >> 6;
            *(float4*)(smf + VT + d * LD + kg * 4) = vr[i];
        }
    };

    {   // prologue: K(0), V(0,0)
        float4 kr[4], vr[4];
#pragma unroll
        for (int i = 0; i < 4; i++) ldK(0, i, kr);
        ldV(0, 0, vr);
#pragma unroll
        for (int i = 0; i < 4; i++) stK(i, kr);
        stV(vr);
    }
    __syncthreads();

    float o[NV][4][4];
#pragma unroll
    for (int a = 0; a < NV; a++)
#pragma unroll
        for (int b = 0; b < 4; b++)
#pragma unroll
            for (int c = 0; c < 4; c++) o[a][b][c] = 0.0f;
    float rs2[2] = {0.0f, 0.0f};

    // MMA2 helper as macro-ish lambda: O_v += P * V_v  (V in VT)
    auto mma2 = [&](float (*ov)[4]) {
#pragma unroll
        for (int kp = 0; kp < 4; kp++) {
            uint32_t bv[4][4];
#pragma unroll
            for (int nt = 0; nt < 4; nt++) {
                uint32_t rowoff = (uint32_t)((kb1 + 8 * nt + br) * LD + kp * 16 + bc);
                LDSM4(bv[nt][0], bv[nt][1], bv[nt][2], bv[nt][3], sb + ((VT + rowoff) << 2));
            }
#pragma unroll
            for (int sub = 0; sub < 2; sub++) {
                int ks = kp * 2 + sub;
                uint32_t ap[4];
                uint32_t rowoff = (uint32_t)((qb1 + ar) * LD + ks * 8 + ac);
                LDSM4(ap[0], ap[1], ap[2], ap[3], sb + ((PS + rowoff) << 2));
#pragma unroll
                for (int nt = 0; nt < 4; nt++)
                    MMA8(ov[nt], ap, bv[nt][2 * sub], bv[nt][2 * sub + 1]);
            }
        }
    };

    for (int kt = 0; kt < 8; kt++) {
        // ============ MMA1: S[64,64] = Q K^T (3x tf32 split) ==============
        float s[4][4];
#pragma unroll
        for (int b = 0; b < 4; b++)
#pragma unroll
            for (int c = 0; c < 4; c++) s[b][c] = 0.0f;

#pragma unroll
        for (int kp = 0; kp < 4; kp++) {
            uint32_t bhi[4][4], blo[4][4];
#pragma unroll
            for (int nt = 0; nt < 4; nt++) {
                uint32_t rowoff = (uint32_t)((kb1 + 8 * nt + br) * LD + kp * 16 + bc);
                LDSM4(bhi[nt][0], bhi[nt][1], bhi[nt][2], bhi[nt][3], sb + ((KHI + rowoff) << 2));
                LDSM4(blo[nt][0], blo[nt][1], blo[nt][2], blo[nt][3], sb + ((KLO + rowoff) << 2));
            }
#pragma unroll
            for (int sub = 0; sub < 2; sub++) {
                int ks = kp * 2 + sub;
                uint32_t ah[4], al[4];
                uint32_t rowoff = (uint32_t)((qb1 + ar) * LD + ks * 8 + ac);
                LDSM4(ah[0], ah[1], ah[2], ah[3], sb + ((QHI + rowoff) << 2));
                LDSM4(al[0], al[1], al[2], al[3], sb + ((QLO + rowoff) << 2));
#pragma unroll
                for (int nt = 0; nt < 4; nt++) {
                    MMA8(s[nt], ah, bhi[nt][2 * sub], bhi[nt][2 * sub + 1]);
                    MMA8(s[nt], al, bhi[nt][2 * sub], bhi[nt][2 * sub + 1]);
                    MMA8(s[nt], ah, blo[nt][2 * sub], blo[nt][2 * sub + 1]);
                }
            }
        }

        // ============ softmax + fused threefry dropout -> P ===============
#pragma unroll
        for (int dr = 0; dr < 2; dr++) {
            int row = qb1 + 8 * dr + g;
            uint32_t gidx = (rowbase + (uint32_t)row) * 512u + (uint32_t)(kt * 64 + kb1);
            float psum = 0.0f;
#pragma unroll
            for (int nt = 0; nt < 4; nt++) {
                uint32_t c0 = gidx + (uint32_t)(8 * nt + 2 * i4);
                float e0 = __expf(s[nt][dr * 2 + 0] * scale);
                float e1 = __expf(s[nt][dr * 2 + 1] * scale);
                psum += e0 + e1;
                float2 pr;
                pr.x = rna_tf32(KEEP(threefry_word(c0)) ? e0 : 0.0f);
                pr.y = rna_tf32(KEEP(threefry_word(c0 + 1u)) ? e1 : 0.0f);
                *(float2*)(smf + PS + row * LD + kb1 + 8 * nt + 2 * i4) = pr;
            }
            rs2[dr] += psum;
        }
        __syncthreads();   // B1: P visible; K free; VT = V(kt,0)

        {
            float4 kr[4];
            if (kt < 7) {
#pragma unroll
                for (int i = 0; i < 4; i++) ldK(kt + 1, i, kr);
            }

            mma2(o[0]);                        // V(kt,0)
            float4 vr[4];
            ldV(kt, 1, vr);
            __syncthreads();                   // B2: VT reads done
            if (kt < 7) {
#pragma unroll
                for (int i = 0; i < 4; i++) stK(i, kr);   // K(kt+1) -> smem
            }
            stV(vr);                           // VT = V(kt,1)
            __syncthreads();                   // B3
        }

        mma2(o[1]);                            // V(kt,1)
        {
            float4 vr[4];
            ldV(kt, 2, vr);
            __syncthreads();                   // B4
            stV(vr);                           // VT = V(kt,2)
            __syncthreads();                   // B5
        }

        mma2(o[2]);                            // V(kt,2)
        {
            float4 vr[4];
            if (kt < 7) ldV(kt + 1, 0, vr);
            __syncthreads();                   // B6: VT reads done; K(kt+1) visible
            if (kt < 7) stV(vr);               // VT = V(kt+1,0); visible by next B1
        }
    }

    // ---- row-sum reduction (denominator includes dropped elems) ----
#pragma unroll
    for (int dr = 0; dr < 2; dr++) {
        float v = rs2[dr];
        v += __shfl_xor_sync(0xffffffffu, v, 1);
        v += __shfl_xor_sync(0xffffffffu, v, 2);
        if (i4 == 0) atomicAdd(&smf[RS + qb1 + 8 * dr + g], v);
    }
    __syncthreads();
    if (tid < 64) smf[RS + tid] = 1.0f / (smf[RS + tid] * 0.65f);
    __syncthreads();

    // ---- epilogue: normalize + store ----
#pragma unroll
    for (int dr = 0; dr < 2; dr++) {
        int row = qb1 + 8 * dr + g;
        float inv = smf[RS + row];
#pragma unroll
        for (int v = 0; v < NV; v++)
#pragma unroll
            for (int nt = 0; nt < 4; nt++) {
                int col = kb1 + 8 * nt + 2 * i4;
                float2 w;
                w.x = o[v][nt][dr * 2 + 0] * inv;
                w.y = o[v][nt][dr * 2 + 1] * inv;
                *(float2*)(out + (((size_t)bh * NV + v) * S_LEN + q0 + row) * D_HEAD + col) = w;
            }
    }
}

// ---------------------------------------------------------------------------
extern "C" void kernel_launch(void* const* d_in, const int* in_sizes, int n_in,
                              void* d_out, int out_size) {
    const float* t0 = (const float*)d_in[0];
    const float* t1 = (const float*)d_in[1];
    const float* t2 = (const float*)d_in[2];
    const float* t3 = (const float*)d_in[3];
    float* out = (float*)d_out;

    static bool attr_set = false;
    if (!attr_set) {
        cudaFuncSetAttribute(attn_mma, cudaFuncAttributeMaxDynamicSharedMemorySize,
                             SM_FLOATS * (int)sizeof(float));
        attr_set = true;
    }

    attn_mma<<<BHC * 8, 256, SM_FLOATS * sizeof(float)>>>(t0, t1, t2, t3, out);
}